// round 11
// baseline (speedup 1.0000x reference)
#include <cuda_runtime.h>
#include <cuda_fp16.h>
#include <cstdint>

typedef unsigned long long ull;

// Problem constants
constexpr int NN = 100000;
constexpr int EE = 1250000;
constexpr int KTOT = 576;                 // 64 (root) + 8*64
constexpr int NK = NN * 8;                // (dst, rel) keys
constexpr int NBLK2 = (NK + 1023) / 1024; // 782 scan blocks
constexpr int NCH = 9;                    // 1 root chunk + 8 relation chunks
constexpr int AS = 72;                    // fp16 A/B smem row stride (144 B)
constexpr int EGRID = (EE + 255) / 256;   // 4883
constexpr int PG1 = (64 * KTOT) / 256;    // 144 blocks for W1 prep
constexpr int PG2 = (32 * KTOT) / 256;    // 72 blocks for W2 prep

// ---------------- scratch ---------------------------------------------------
__device__ int g_cnt[NK];                 // zero at load; re-zeroed by k_scan
__device__ int g_rowptr[NK + 1];          // +1 sentinel (= EE)
__device__ int g_cursor[NK];
__device__ int g_epack[EE];               // src ids sorted by (dst, rel)
__device__ unsigned int g_scanflag[NBLK2];// decoupled-lookback flags (zeroed by k_count)
__device__ float g_H[(size_t)NN * 64];
__device__ __half g_Wt1h[64 * KTOT];
__device__ __half g_Wt1l[64 * KTOT];
__device__ __half g_Wt2h[32 * KTOT];
__device__ __half g_Wt2l[32 * KTOT];

// ---------------- helpers ---------------------------------------------------
__device__ __forceinline__ uint32_t smem_u32(const void* p) {
    uint32_t a;
    asm("{ .reg .u64 t; cvta.to.shared.u64 t, %1; cvt.u32.u64 %0, t; }" : "=r"(a) : "l"(p));
    return a;
}
__device__ __forceinline__ void sts128(uint32_t a, uint32_t x, uint32_t y, uint32_t z, uint32_t w) {
    asm volatile("st.shared.v4.b32 [%0], {%1,%2,%3,%4};" :: "r"(a), "r"(x), "r"(y), "r"(z), "r"(w) : "memory");
}
__device__ __forceinline__ void sts64(uint32_t a, uint32_t x, uint32_t y) {
    asm volatile("st.shared.v2.b32 [%0], {%1,%2};" :: "r"(a), "r"(x), "r"(y) : "memory");
}
__device__ __forceinline__ uint32_t lds32(uint32_t a) {
    uint32_t v;
    asm volatile("ld.shared.b32 %0, [%1];" : "=r"(v) : "r"(a));
    return v;
}
__device__ __forceinline__ uint32_t cvt2h(float lo, float hi) {
    uint32_t r;
    asm("cvt.rn.satfinite.f16x2.f32 %0, %1, %2;" : "=r"(r) : "f"(hi), "f"(lo));
    return r;
}
__device__ __forceinline__ void ldmx4(uint32_t* r, uint32_t a) {
    asm volatile("ldmatrix.sync.aligned.m8n8.x4.shared.b16 {%0,%1,%2,%3}, [%4];"
                 : "=r"(r[0]), "=r"(r[1]), "=r"(r[2]), "=r"(r[3]) : "r"(a));
}
__device__ __forceinline__ void mma16816(float* c, const uint32_t* a, uint32_t b0, uint32_t b1) {
    asm volatile("mma.sync.aligned.m16n8k16.row.col.f32.f16.f16.f32 "
                 "{%0,%1,%2,%3}, {%4,%5,%6,%7}, {%8,%9}, {%0,%1,%2,%3};"
                 : "+f"(c[0]), "+f"(c[1]), "+f"(c[2]), "+f"(c[3])
                 : "r"(a[0]), "r"(a[1]), "r"(a[2]), "r"(a[3]), "r"(b0), "r"(b1));
}
__device__ __forceinline__ void pf_l1(const void* p) {
    asm volatile("prefetch.global.L1 [%0];" :: "l"(p));
}

// ---------------- CSR build over keys (dst*8 + rel) --------------------------
__global__ void k_count(const int* __restrict__ dst, const int* __restrict__ et) {
    int e = blockIdx.x * blockDim.x + threadIdx.x;
    if (e < NBLK2) g_scanflag[e] = 0;   // reset lookback flags for k_scan
    if (e < EE) atomicAdd(&g_cnt[dst[e] * 8 + et[e]], 1);
}

// single-pass decoupled-lookback exclusive scan over g_cnt -> g_rowptr/g_cursor
__global__ void k_scan() {
    int t = threadIdx.x, b = blockIdx.x, i = b * 1024 + t;
    int lane = t & 31, wid = t >> 5;
    int orig = 0;
    if (i < NK) {
        orig = g_cnt[i];
        g_cnt[i] = 0;  // pre-zero for next call
    }
    int v = orig;
#pragma unroll
    for (int o = 1; o < 32; o <<= 1) {
        int nv = __shfl_up_sync(0xffffffffu, v, o);
        if (lane >= o) v += nv;
    }
    __shared__ int ws[32];
    __shared__ int s_prefix;
    if (lane == 31) ws[wid] = v;
    __syncthreads();
    if (wid == 0) {
        int wv = ws[lane];
#pragma unroll
        for (int o = 1; o < 32; o <<= 1) {
            int nv = __shfl_up_sync(0xffffffffu, wv, o);
            if (lane >= o) wv += nv;
        }
        ws[lane] = wv;
    }
    __syncthreads();
    int wpre = wid ? ws[wid - 1] : 0;
    int incl = wpre + v;                 // inclusive within block
    if (t == 0) {
        int total = ws[31];
        if (b == 0) {
            atomicExch(&g_scanflag[0], ((unsigned)total << 2) | 2u);
            s_prefix = 0;
        } else {
            atomicExch(&g_scanflag[b], ((unsigned)total << 2) | 1u);
            int prefix = 0;
            for (int pb = b - 1;;) {
                unsigned wv;
                do { wv = atomicAdd(&g_scanflag[pb], 0u); } while ((wv & 3u) == 0u);
                prefix += (int)(wv >> 2);
                if ((wv & 3u) == 2u) break;
                pb--;
            }
            atomicExch(&g_scanflag[b], ((unsigned)(prefix + total) << 2) | 2u);
            s_prefix = prefix;
        }
    }
    __syncthreads();
    int prefix = s_prefix;
    if (i < NK) {
        int rv = prefix + incl - orig;   // exclusive prefix
        g_rowptr[i] = rv;
        g_cursor[i] = rv;
    }
    if (i == 0) g_rowptr[NK] = EE;       // sentinel
}

// ---------------- merged: edge build + W transpose + fp16 hi/lo split --------
__device__ __forceinline__ void prep_one(const float* __restrict__ root,
                                         const float* __restrict__ W,
                                         __half* __restrict__ oh,
                                         __half* __restrict__ ol,
                                         int dout, int i) {
    int n = i / KTOT, k = i % KTOT;
    float v = (k < 64) ? root[k * dout + n] : W[(size_t)(k - 64) * dout + n];
    __half h = __float2half_rn(v);
    float lo = v - __half2float(h);
    oh[i] = h;
    ol[i] = __float2half_rn(lo);
}
__global__ void k_build_prep(const int* __restrict__ src, const int* __restrict__ dst,
                             const int* __restrict__ et,
                             const float* __restrict__ root1, const float* __restrict__ W1,
                             const float* __restrict__ root2, const float* __restrict__ W2) {
    int b = blockIdx.x;
    if (b < EGRID) {
        int e = b * 256 + threadIdx.x;
        if (e < EE) {
            int p = atomicAdd(&g_cursor[dst[e] * 8 + et[e]], 1);
            g_epack[p] = src[e];
        }
    } else if (b < EGRID + PG1) {
        prep_one(root1, W1, g_Wt1h, g_Wt1l, 64, (b - EGRID) * 256 + threadIdx.x);
    } else {
        prep_one(root2, W2, g_Wt2h, g_Wt2l, 32, (b - EGRID - PG1) * 256 + threadIdx.x);
    }
}

// ---------------- fused 8-lane/row gather + mma.sync fp16 2-pass GEMM -------
// Gather with L1 prefetch pipeline: next edge's 2 lines prefetched while the
// current edge's (already prefetched) values are loaded + accumulated.
template <int DOUT, bool RELU>
__global__ __launch_bounds__(256, 2) void k_gemm_fused(
    const float* __restrict__ X,
    const __half* __restrict__ Wth, const __half* __restrict__ Wtl,
    const float* __restrict__ bias, float* __restrict__ out) {
    constexpr int NT = DOUT / 8;            // n-tiles per warp
    constexpr int BP = 256 / DOUT;          // B copy: parts per row
    constexpr int BV = (64 * 2 / BP) / 16;  // uint4 per thread per B buffer

    extern __shared__ __align__(16) char dyn[];
    uint32_t sA = smem_u32(dyn);
    uint32_t sBh = sA + 128 * AS * 2;
    uint32_t sBl = sBh + DOUT * AS * 2;

    int tid = threadIdx.x;
    int w = tid >> 5, l = tid & 31;
    int m0 = blockIdx.x * 128;

    int jl = l & 7;   // col part (32 B of the fp32 row)
    int ns = l >> 3;  // node sub-index within warp group of 4
    int pfoff = (jl & 4) << 5;  // lanes 0-3 prefetch line 0, lanes 4-7 line 1

    // B copy mapping
    int bn = tid % DOUT, bpart = tid / DOUT;
    uint4 bh4[BV], bl4[BV];
    auto loadB = [&](int c) {
        size_t off = (size_t)bn * KTOT + c * 64;
        const uint4* bh = reinterpret_cast<const uint4*>(Wth + off) + bpart * BV;
        const uint4* bl = reinterpret_cast<const uint4*>(Wtl + off) + bpart * BV;
#pragma unroll
        for (int v = 0; v < BV; v++) { bh4[v] = bh[v]; bl4[v] = bl[v]; }
    };
    auto storeB = [&]() {
        uint32_t bbase = (uint32_t)(bn * (AS * 2) + bpart * (BV * 16));
#pragma unroll
        for (int v = 0; v < BV; v++) {
            sts128(sBh + bbase + v * 16, bh4[v].x, bh4[v].y, bh4[v].z, bh4[v].w);
            sts128(sBl + bbase + v * 16, bl4[v].x, bl4[v].y, bl4[v].z, bl4[v].w);
        }
    };

    // convert 8 floats (2 float4) of row nrow, col part jl -> fp16 in sA
    auto cvst = [&](int nrow, float4 v0, float4 v1, float inv) {
        v0.x *= inv; v0.y *= inv; v0.z *= inv; v0.w *= inv;
        v1.x *= inv; v1.y *= inv; v1.z *= inv; v1.w *= inv;
        uint32_t h0 = cvt2h(v0.x, v0.y), h1 = cvt2h(v0.z, v0.w);
        uint32_t h2 = cvt2h(v1.x, v1.y), h3 = cvt2h(v1.z, v1.w);
        uint32_t base = (uint32_t)(nrow * (AS * 2)) + jl * 8;
        sts64(sA + base, h0, h1);
        sts64(sA + base + 64, h2, h3);
    };

    float acc[NT][4];
#pragma unroll
    for (int t = 0; t < NT; t++)
#pragma unroll
        for (int q = 0; q < 4; q++) acc[t][q] = 0.f;

    // A ldmatrix address
    int lrow = w * 16 + (l & 7) + ((l >> 3) & 1) * 8;
    uint32_t aoff = (uint32_t)(lrow * (AS * 2)) + ((l >> 4) & 1) * 16;
    // B frag address components
    int bfn = l >> 2;
    int bfk = (l & 3) * 4;

    loadB(0);
    for (int c = 0; c < NCH; c++) {
        storeB();
        // ---- build A chunk c ----
        if (c == 0) {
#pragma unroll
            for (int p = 0; p < 4; p++) {
                int mg = m0 + w * 16 + p * 4 + ns;
                float4 v0 = make_float4(0.f, 0.f, 0.f, 0.f), v1 = v0;
                if (mg < NN) {
                    const float4* xp = reinterpret_cast<const float4*>(X + (size_t)mg * 64);
                    v0 = xp[jl];
                    v1 = xp[8 + jl];
                }
                cvst(w * 16 + p * 4 + ns, v0, v1, 1.0f);
            }
        } else {
            int r = c - 1;
            int st[4], cn[4];
#pragma unroll
            for (int p = 0; p < 4; p++) {
                int mg = m0 + w * 16 + p * 4 + ns;
                if (mg < NN) {
                    int key = mg * 8 + r;
                    int s0 = __ldg(g_rowptr + key);
                    st[p] = s0;
                    cn[p] = __ldg(g_rowptr + key + 1) - s0;
                } else {
                    st[p] = 0;
                    cn[p] = 0;
                }
            }
            int mx = max(max(cn[0], cn[1]), max(cn[2], cn[3]));
            float4 a0[4], a1[4];
#pragma unroll
            for (int p = 0; p < 4; p++) {
                a0[p] = make_float4(0.f, 0.f, 0.f, 0.f);
                a1[p] = make_float4(0.f, 0.f, 0.f, 0.f);
            }
            int rec[4], nrc[4];
#pragma unroll
            for (int p = 0; p < 4; p++)
                rec[p] = (cn[p] > 0) ? __ldg(g_epack + st[p]) : -1;
            // prefetch first edge's lines (partial warm for iter 0)
#pragma unroll
            for (int p = 0; p < 4; p++)
                if (rec[p] >= 0)
                    pf_l1((const char*)(X + (size_t)rec[p] * 64) + pfoff);
            for (int j = 0; j < mx; j++) {
                // current values (prefetched)
                float4 v0[4], v1[4];
#pragma unroll
                for (int p = 0; p < 4; p++) {
                    if (rec[p] >= 0) {
                        const float4* xp = reinterpret_cast<const float4*>(X + (size_t)rec[p] * 64);
                        v0[p] = xp[jl];
                        v1[p] = xp[8 + jl];
                    }
                }
                // next records + prefetch their lines
#pragma unroll
                for (int p = 0; p < 4; p++)
                    nrc[p] = (j + 1 < cn[p]) ? __ldg(g_epack + st[p] + j + 1) : -1;
#pragma unroll
                for (int p = 0; p < 4; p++)
                    if (nrc[p] >= 0)
                        pf_l1((const char*)(X + (size_t)nrc[p] * 64) + pfoff);
                // accumulate
#pragma unroll
                for (int p = 0; p < 4; p++) {
                    if (rec[p] >= 0) {
                        a0[p].x += v0[p].x; a0[p].y += v0[p].y;
                        a0[p].z += v0[p].z; a0[p].w += v0[p].w;
                        a1[p].x += v1[p].x; a1[p].y += v1[p].y;
                        a1[p].z += v1[p].z; a1[p].w += v1[p].w;
                    }
                    rec[p] = nrc[p];
                }
            }
#pragma unroll
            for (int p = 0; p < 4; p++) {
                float inv = 1.0f / (float)max(cn[p], 1);
                cvst(w * 16 + p * 4 + ns, a0[p], a1[p], inv);
            }
        }
        __syncthreads();
        if (c + 1 < NCH) loadB(c + 1);
        // ---- MMA for chunk c (2 passes: A*Bh + A*Bl) ----
#pragma unroll
        for (int ks = 0; ks < 4; ks++) {
            uint32_t fa[4];
            ldmx4(fa, sA + aoff + ks * 32);
#pragma unroll
            for (int t = 0; t < NT; t++) {
                uint32_t ba = (uint32_t)((t * 8 + bfn) * (AS * 2)) + ks * 32 + bfk;
                uint32_t bh0 = lds32(sBh + ba), bh1 = lds32(sBh + ba + 16);
                uint32_t bl0 = lds32(sBl + ba), bl1 = lds32(sBl + ba + 16);
                mma16816(acc[t], fa, bh0, bh1);
                mma16816(acc[t], fa, bl0, bl1);
            }
        }
        __syncthreads();
    }

    // epilogue
    int r0 = m0 + w * 16 + (l >> 2);
    int cb = (l & 3) * 2;
#pragma unroll
    for (int t = 0; t < NT; t++) {
        int n = t * 8 + cb;
        float b0 = __ldg(bias + n), b1 = __ldg(bias + n + 1);
        if (r0 < NN) {
            float v0 = acc[t][0] + b0, v1 = acc[t][1] + b1;
            if (RELU) { v0 = fmaxf(v0, 0.f); v1 = fmaxf(v1, 0.f); }
            *reinterpret_cast<float2*>(out + (size_t)r0 * DOUT + n) = make_float2(v0, v1);
        }
        if (r0 + 8 < NN) {
            float v2 = acc[t][2] + b0, v3 = acc[t][3] + b1;
            if (RELU) { v2 = fmaxf(v2, 0.f); v3 = fmaxf(v3, 0.f); }
            *reinterpret_cast<float2*>(out + (size_t)(r0 + 8) * DOUT + n) = make_float2(v2, v3);
        }
    }
}

// ---------------- launch ----------------------------------------------------
extern "C" void kernel_launch(void* const* d_in, const int* in_sizes, int n_in,
                              void* d_out, int out_size) {
    const float* x     = (const float*)d_in[0];
    const float* W1    = (const float*)d_in[1];
    const float* root1 = (const float*)d_in[2];
    const float* b1    = (const float*)d_in[3];
    const float* W2    = (const float*)d_in[4];
    const float* root2 = (const float*)d_in[5];
    const float* b2    = (const float*)d_in[6];
    const int*   src   = (const int*)d_in[7];
    const int*   dst   = (const int*)d_in[8];
    const int*   et    = (const int*)d_in[9];
    float* out = (float*)d_out;

    float* H;
    __half *w1h, *w1l, *w2h, *w2l;
    cudaGetSymbolAddress((void**)&H, g_H);
    cudaGetSymbolAddress((void**)&w1h, g_Wt1h);
    cudaGetSymbolAddress((void**)&w1l, g_Wt1l);
    cudaGetSymbolAddress((void**)&w2h, g_Wt2h);
    cudaGetSymbolAddress((void**)&w2l, g_Wt2l);

    const int ggrid = (NN + 127) / 128;
    const int smA = 128 * AS * 2;
    const int smem64 = smA + 2 * 64 * AS * 2;   // 36864
    const int smem32 = smA + 2 * 32 * AS * 2;   // 27648

    static bool attr_done = false;
    if (!attr_done) {
        cudaFuncSetAttribute(k_gemm_fused<64, true>,
                             cudaFuncAttributeMaxDynamicSharedMemorySize, smem64);
        cudaFuncSetAttribute(k_gemm_fused<32, false>,
                             cudaFuncAttributeMaxDynamicSharedMemorySize, smem32);
        attr_done = true;
    }

    // CSR build over (dst, rel) keys (g_cnt pre-zeroed by previous call's k_scan)
    k_count<<<EGRID, 256>>>(dst, et);
    k_scan<<<NBLK2, 1024>>>();
    k_build_prep<<<EGRID + PG1 + PG2, 256>>>(src, dst, et, root1, W1, root2, W2);

    // Layer 1 (fused aggregate+GEMM)
    k_gemm_fused<64, true><<<ggrid, 256, smem64>>>(x, w1h, w1l, b1, H);

    // Layer 2
    k_gemm_fused<32, false><<<ggrid, 256, smem32>>>(H, w2h, w2l, b2, out);
}

// round 12
// speedup vs baseline: 1.1394x; 1.1394x over previous
#include <cuda_runtime.h>
#include <cuda_fp16.h>
#include <cstdint>

typedef unsigned long long ull;

// Problem constants
constexpr int NN = 100000;
constexpr int EE = 1250000;
constexpr int KTOT = 576;                 // 64 (root) + 8*64
constexpr int NK = NN * 8;                // (dst, rel) keys
constexpr int NBLK2 = (NK + 1023) / 1024; // 782 scan blocks
constexpr int NCH = 9;                    // 1 root chunk + 8 relation chunks
constexpr int AS = 72;                    // fp16 A/B smem row stride (144 B)
constexpr int EGRID = (EE + 255) / 256;   // 4883
constexpr int PG1 = (64 * KTOT) / 256;    // 144 blocks for W1 prep
constexpr int PG2 = (32 * KTOT) / 256;    // 72 blocks for W2 prep
constexpr int XG = (NN * 64) / (256 * 8); // 3125 blocks for x->fp16 convert

// ---------------- scratch ---------------------------------------------------
__device__ int g_cnt[NK];                 // zero at load; re-zeroed by k_scan
__device__ int g_rowptr[NK + 1];          // +1 sentinel (= EE)
__device__ int g_cursor[NK];
__device__ int g_epack[EE];               // src ids sorted by (dst, rel)
__device__ unsigned int g_scanflag[NBLK2];// decoupled-lookback flags (zeroed by k_count)
__device__ __half g_x16[(size_t)NN * 64]; // fp16 copy of input features
__device__ __half g_H[(size_t)NN * 64];   // fp16 hidden layer
__device__ __half g_Wt1h[64 * KTOT];
__device__ __half g_Wt1l[64 * KTOT];
__device__ __half g_Wt2h[32 * KTOT];
__device__ __half g_Wt2l[32 * KTOT];

// ---------------- helpers ---------------------------------------------------
__device__ __forceinline__ uint32_t smem_u32(const void* p) {
    uint32_t a;
    asm("{ .reg .u64 t; cvta.to.shared.u64 t, %1; cvt.u32.u64 %0, t; }" : "=r"(a) : "l"(p));
    return a;
}
__device__ __forceinline__ void sts128(uint32_t a, uint32_t x, uint32_t y, uint32_t z, uint32_t w) {
    asm volatile("st.shared.v4.b32 [%0], {%1,%2,%3,%4};" :: "r"(a), "r"(x), "r"(y), "r"(z), "r"(w) : "memory");
}
__device__ __forceinline__ uint32_t lds32(uint32_t a) {
    uint32_t v;
    asm volatile("ld.shared.b32 %0, [%1];" : "=r"(v) : "r"(a));
    return v;
}
__device__ __forceinline__ uint32_t cvt2h(float lo, float hi) {
    uint32_t r;
    asm("cvt.rn.satfinite.f16x2.f32 %0, %1, %2;" : "=r"(r) : "f"(hi), "f"(lo));
    return r;
}
__device__ __forceinline__ void ldmx4(uint32_t* r, uint32_t a) {
    asm volatile("ldmatrix.sync.aligned.m8n8.x4.shared.b16 {%0,%1,%2,%3}, [%4];"
                 : "=r"(r[0]), "=r"(r[1]), "=r"(r[2]), "=r"(r[3]) : "r"(a));
}
__device__ __forceinline__ void mma16816(float* c, const uint32_t* a, uint32_t b0, uint32_t b1) {
    asm volatile("mma.sync.aligned.m16n8k16.row.col.f32.f16.f16.f32 "
                 "{%0,%1,%2,%3}, {%4,%5,%6,%7}, {%8,%9}, {%0,%1,%2,%3};"
                 : "+f"(c[0]), "+f"(c[1]), "+f"(c[2]), "+f"(c[3])
                 : "r"(a[0]), "r"(a[1]), "r"(a[2]), "r"(a[3]), "r"(b0), "r"(b1));
}

// ---------------- CSR build over keys (dst*8 + rel) --------------------------
__global__ void k_count(const int* __restrict__ dst, const int* __restrict__ et) {
    int e = blockIdx.x * blockDim.x + threadIdx.x;
    if (e < NBLK2) g_scanflag[e] = 0;   // reset lookback flags for k_scan
    if (e < EE) atomicAdd(&g_cnt[dst[e] * 8 + et[e]], 1);
}

// single-pass decoupled-lookback exclusive scan over g_cnt -> g_rowptr/g_cursor
__global__ void k_scan() {
    int t = threadIdx.x, b = blockIdx.x, i = b * 1024 + t;
    int lane = t & 31, wid = t >> 5;
    int orig = 0;
    if (i < NK) {
        orig = g_cnt[i];
        g_cnt[i] = 0;  // pre-zero for next call
    }
    int v = orig;
#pragma unroll
    for (int o = 1; o < 32; o <<= 1) {
        int nv = __shfl_up_sync(0xffffffffu, v, o);
        if (lane >= o) v += nv;
    }
    __shared__ int ws[32];
    __shared__ int s_prefix;
    if (lane == 31) ws[wid] = v;
    __syncthreads();
    if (wid == 0) {
        int wv = ws[lane];
#pragma unroll
        for (int o = 1; o < 32; o <<= 1) {
            int nv = __shfl_up_sync(0xffffffffu, wv, o);
            if (lane >= o) wv += nv;
        }
        ws[lane] = wv;
    }
    __syncthreads();
    int wpre = wid ? ws[wid - 1] : 0;
    int incl = wpre + v;
    if (t == 0) {
        int total = ws[31];
        if (b == 0) {
            atomicExch(&g_scanflag[0], ((unsigned)total << 2) | 2u);
            s_prefix = 0;
        } else {
            atomicExch(&g_scanflag[b], ((unsigned)total << 2) | 1u);
            int prefix = 0;
            for (int pb = b - 1;;) {
                unsigned wv;
                do { wv = atomicAdd(&g_scanflag[pb], 0u); } while ((wv & 3u) == 0u);
                prefix += (int)(wv >> 2);
                if ((wv & 3u) == 2u) break;
                pb--;
            }
            atomicExch(&g_scanflag[b], ((unsigned)(prefix + total) << 2) | 2u);
            s_prefix = prefix;
        }
    }
    __syncthreads();
    int prefix = s_prefix;
    if (i < NK) {
        int rv = prefix + incl - orig;
        g_rowptr[i] = rv;
        g_cursor[i] = rv;
    }
    if (i == 0) g_rowptr[NK] = EE;
}

// ------- merged: edge build + W transpose/split + x -> fp16 convert ----------
__device__ __forceinline__ void prep_one(const float* __restrict__ root,
                                         const float* __restrict__ W,
                                         __half* __restrict__ oh,
                                         __half* __restrict__ ol,
                                         int dout, int i) {
    int n = i / KTOT, k = i % KTOT;
    float v = (k < 64) ? root[k * dout + n] : W[(size_t)(k - 64) * dout + n];
    __half h = __float2half_rn(v);
    float lo = v - __half2float(h);
    oh[i] = h;
    ol[i] = __float2half_rn(lo);
}
__global__ void k_build_prep(const int* __restrict__ src, const int* __restrict__ dst,
                             const int* __restrict__ et, const float* __restrict__ x,
                             const float* __restrict__ root1, const float* __restrict__ W1,
                             const float* __restrict__ root2, const float* __restrict__ W2) {
    int b = blockIdx.x;
    if (b < EGRID) {
        int e = b * 256 + threadIdx.x;
        if (e < EE) {
            int p = atomicAdd(&g_cursor[dst[e] * 8 + et[e]], 1);
            g_epack[p] = src[e];
        }
    } else if (b < EGRID + XG) {
        // convert 8 floats -> 8 halfs per thread
        size_t i = ((size_t)(b - EGRID) * 256 + threadIdx.x) * 8;
        const float4* xp = reinterpret_cast<const float4*>(x + i);
        float4 v0 = xp[0], v1 = xp[1];
        uint4 o;
        o.x = cvt2h(v0.x, v0.y);
        o.y = cvt2h(v0.z, v0.w);
        o.z = cvt2h(v1.x, v1.y);
        o.w = cvt2h(v1.z, v1.w);
        *reinterpret_cast<uint4*>(g_x16 + i) = o;
    } else if (b < EGRID + XG + PG1) {
        prep_one(root1, W1, g_Wt1h, g_Wt1l, 64, (b - EGRID - XG) * 256 + threadIdx.x);
    } else {
        prep_one(root2, W2, g_Wt2h, g_Wt2l, 32, (b - EGRID - XG - PG1) * 256 + threadIdx.x);
    }
}

// ---------------- fused fp16-gather + mma.sync fp16 2-pass GEMM -------------
// Gather from fp16 features: 1 L1 line (1 wavefront) per edge. Warp = 4 node
// groups x 8 lanes; lane owns 16 B (8 halfs) of the 128 B row. fp32 register
// accumulation after half2 unpack. OUT16: write result as fp16 (hidden layer).
template <int DOUT, bool RELU, bool OUT16>
__global__ __launch_bounds__(256, 2) void k_gemm_fused(
    const __half* __restrict__ X16,
    const __half* __restrict__ Wth, const __half* __restrict__ Wtl,
    const float* __restrict__ bias, void* __restrict__ outv) {
    constexpr int NT = DOUT / 8;            // n-tiles per warp
    constexpr int BP = 256 / DOUT;          // B copy: parts per row
    constexpr int BV = (64 * 2 / BP) / 16;  // uint4 per thread per B buffer

    extern __shared__ __align__(16) char dyn[];
    uint32_t sA = smem_u32(dyn);
    uint32_t sBh = sA + 128 * AS * 2;
    uint32_t sBl = sBh + DOUT * AS * 2;

    int tid = threadIdx.x;
    int w = tid >> 5, l = tid & 31;
    int m0 = blockIdx.x * 128;

    int jl = l & 7;   // 16-B part of the 128-B fp16 row (cols 8jl..8jl+7)
    int ns = l >> 3;  // node sub-index within warp group of 4

    // B copy mapping
    int bn = tid % DOUT, bpart = tid / DOUT;
    uint4 bh4[BV], bl4[BV];
    auto loadB = [&](int c) {
        size_t off = (size_t)bn * KTOT + c * 64;
        const uint4* bh = reinterpret_cast<const uint4*>(Wth + off) + bpart * BV;
        const uint4* bl = reinterpret_cast<const uint4*>(Wtl + off) + bpart * BV;
#pragma unroll
        for (int v = 0; v < BV; v++) { bh4[v] = bh[v]; bl4[v] = bl[v]; }
    };
    auto storeB = [&]() {
        uint32_t bbase = (uint32_t)(bn * (AS * 2) + bpart * (BV * 16));
#pragma unroll
        for (int v = 0; v < BV; v++) {
            sts128(sBh + bbase + v * 16, bh4[v].x, bh4[v].y, bh4[v].z, bh4[v].w);
            sts128(sBl + bbase + v * 16, bl4[v].x, bl4[v].y, bl4[v].z, bl4[v].w);
        }
    };

    float acc[NT][4];
#pragma unroll
    for (int t = 0; t < NT; t++)
#pragma unroll
        for (int q = 0; q < 4; q++) acc[t][q] = 0.f;

    // A ldmatrix address
    int lrow = w * 16 + (l & 7) + ((l >> 3) & 1) * 8;
    uint32_t aoff = (uint32_t)(lrow * (AS * 2)) + ((l >> 4) & 1) * 16;
    // B frag address components
    int bfn = l >> 2;
    int bfk = (l & 3) * 4;

    loadB(0);
    for (int c = 0; c < NCH; c++) {
        storeB();
        // ---- build A chunk c ----
        if (c == 0) {
#pragma unroll
            for (int p = 0; p < 4; p++) {
                int nrow = w * 16 + p * 4 + ns;
                int mg = m0 + nrow;
                uint4 v = make_uint4(0u, 0u, 0u, 0u);
                if (mg < NN)
                    v = *(reinterpret_cast<const uint4*>(X16 + (size_t)mg * 64) + jl);
                sts128(sA + (uint32_t)(nrow * (AS * 2)) + jl * 16, v.x, v.y, v.z, v.w);
            }
        } else {
            int r = c - 1;
            int st[4], cn[4];
#pragma unroll
            for (int p = 0; p < 4; p++) {
                int mg = m0 + w * 16 + p * 4 + ns;
                if (mg < NN) {
                    int key = mg * 8 + r;
                    int s0 = __ldg(g_rowptr + key);
                    st[p] = s0;
                    cn[p] = __ldg(g_rowptr + key + 1) - s0;
                } else {
                    st[p] = 0;
                    cn[p] = 0;
                }
            }
            int mx = max(max(cn[0], cn[1]), max(cn[2], cn[3]));
            float4 a0[4], a1[4];
#pragma unroll
            for (int p = 0; p < 4; p++) {
                a0[p] = make_float4(0.f, 0.f, 0.f, 0.f);
                a1[p] = make_float4(0.f, 0.f, 0.f, 0.f);
            }
            int rec[4];
#pragma unroll
            for (int p = 0; p < 4; p++)
                rec[p] = (cn[p] > 0) ? __ldg(g_epack + st[p]) : -1;
            for (int j = 0; j < mx; j++) {
                uint4 v[4];
#pragma unroll
                for (int p = 0; p < 4; p++) {
                    if (rec[p] >= 0)
                        v[p] = *(reinterpret_cast<const uint4*>(X16 + (size_t)rec[p] * 64) + jl);
                }
#pragma unroll
                for (int p = 0; p < 4; p++) {
                    bool more = (j + 1 < cn[p]);
                    int nr = more ? __ldg(g_epack + st[p] + j + 1) : -1;
                    if (rec[p] >= 0) {
                        float2 f0 = __half22float2(*reinterpret_cast<__half2*>(&v[p].x));
                        float2 f1 = __half22float2(*reinterpret_cast<__half2*>(&v[p].y));
                        float2 f2 = __half22float2(*reinterpret_cast<__half2*>(&v[p].z));
                        float2 f3 = __half22float2(*reinterpret_cast<__half2*>(&v[p].w));
                        a0[p].x += f0.x; a0[p].y += f0.y;
                        a0[p].z += f1.x; a0[p].w += f1.y;
                        a1[p].x += f2.x; a1[p].y += f2.y;
                        a1[p].z += f3.x; a1[p].w += f3.y;
                    }
                    rec[p] = nr;
                }
            }
#pragma unroll
            for (int p = 0; p < 4; p++) {
                int nrow = w * 16 + p * 4 + ns;
                float inv = 1.0f / (float)max(cn[p], 1);
                uint32_t h0 = cvt2h(a0[p].x * inv, a0[p].y * inv);
                uint32_t h1 = cvt2h(a0[p].z * inv, a0[p].w * inv);
                uint32_t h2 = cvt2h(a1[p].x * inv, a1[p].y * inv);
                uint32_t h3 = cvt2h(a1[p].z * inv, a1[p].w * inv);
                sts128(sA + (uint32_t)(nrow * (AS * 2)) + jl * 16, h0, h1, h2, h3);
            }
        }
        __syncthreads();
        if (c + 1 < NCH) loadB(c + 1);
        // ---- MMA for chunk c (2 passes: A*Bh + A*Bl) ----
#pragma unroll
        for (int ks = 0; ks < 4; ks++) {
            uint32_t fa[4];
            ldmx4(fa, sA + aoff + ks * 32);
#pragma unroll
            for (int t = 0; t < NT; t++) {
                uint32_t ba = (uint32_t)((t * 8 + bfn) * (AS * 2)) + ks * 32 + bfk;
                uint32_t bh0 = lds32(sBh + ba), bh1 = lds32(sBh + ba + 16);
                uint32_t bl0 = lds32(sBl + ba), bl1 = lds32(sBl + ba + 16);
                mma16816(acc[t], fa, bh0, bh1);
                mma16816(acc[t], fa, bl0, bl1);
            }
        }
        __syncthreads();
    }

    // epilogue
    int r0 = m0 + w * 16 + (l >> 2);
    int cb = (l & 3) * 2;
#pragma unroll
    for (int t = 0; t < NT; t++) {
        int n = t * 8 + cb;
        float b0 = __ldg(bias + n), b1 = __ldg(bias + n + 1);
        float v0 = acc[t][0] + b0, v1 = acc[t][1] + b1;
        float v2 = acc[t][2] + b0, v3 = acc[t][3] + b1;
        if (RELU) {
            v0 = fmaxf(v0, 0.f); v1 = fmaxf(v1, 0.f);
            v2 = fmaxf(v2, 0.f); v3 = fmaxf(v3, 0.f);
        }
        if (OUT16) {
            __half* o16 = reinterpret_cast<__half*>(outv);
            if (r0 < NN)
                *reinterpret_cast<uint32_t*>(o16 + (size_t)r0 * DOUT + n) = cvt2h(v0, v1);
            if (r0 + 8 < NN)
                *reinterpret_cast<uint32_t*>(o16 + (size_t)(r0 + 8) * DOUT + n) = cvt2h(v2, v3);
        } else {
            float* of = reinterpret_cast<float*>(outv);
            if (r0 < NN)
                *reinterpret_cast<float2*>(of + (size_t)r0 * DOUT + n) = make_float2(v0, v1);
            if (r0 + 8 < NN)
                *reinterpret_cast<float2*>(of + (size_t)(r0 + 8) * DOUT + n) = make_float2(v2, v3);
        }
    }
}

// ---------------- launch ----------------------------------------------------
extern "C" void kernel_launch(void* const* d_in, const int* in_sizes, int n_in,
                              void* d_out, int out_size) {
    const float* x     = (const float*)d_in[0];
    const float* W1    = (const float*)d_in[1];
    const float* root1 = (const float*)d_in[2];
    const float* b1    = (const float*)d_in[3];
    const float* W2    = (const float*)d_in[4];
    const float* root2 = (const float*)d_in[5];
    const float* b2    = (const float*)d_in[6];
    const int*   src   = (const int*)d_in[7];
    const int*   dst   = (const int*)d_in[8];
    const int*   et    = (const int*)d_in[9];

    __half *H, *x16, *w1h, *w1l, *w2h, *w2l;
    cudaGetSymbolAddress((void**)&H, g_H);
    cudaGetSymbolAddress((void**)&x16, g_x16);
    cudaGetSymbolAddress((void**)&w1h, g_Wt1h);
    cudaGetSymbolAddress((void**)&w1l, g_Wt1l);
    cudaGetSymbolAddress((void**)&w2h, g_Wt2h);
    cudaGetSymbolAddress((void**)&w2l, g_Wt2l);

    const int ggrid = (NN + 127) / 128;
    const int smA = 128 * AS * 2;
    const int smem64 = smA + 2 * 64 * AS * 2;   // 36864
    const int smem32 = smA + 2 * 32 * AS * 2;   // 27648

    static bool attr_done = false;
    if (!attr_done) {
        cudaFuncSetAttribute(k_gemm_fused<64, true, true>,
                             cudaFuncAttributeMaxDynamicSharedMemorySize, smem64);
        cudaFuncSetAttribute(k_gemm_fused<32, false, false>,
                             cudaFuncAttributeMaxDynamicSharedMemorySize, smem32);
        attr_done = true;
    }

    // CSR build over (dst, rel) keys (g_cnt pre-zeroed by previous call's k_scan)
    k_count<<<EGRID, 256>>>(dst, et);
    k_scan<<<NBLK2, 1024>>>();
    k_build_prep<<<EGRID + XG + PG1 + PG2, 256>>>(src, dst, et, x,
                                                  root1, W1, root2, W2);

    // Layer 1 (fused aggregate+GEMM), H written fp16
    k_gemm_fused<64, true, true><<<ggrid, 256, smem64>>>(x16, w1h, w1l, b1, H);

    // Layer 2 -> fp32 output
    k_gemm_fused<32, false, false><<<ggrid, 256, smem32>>>(H, w2h, w2l, b2, d_out);
}

// round 13
// speedup vs baseline: 1.1820x; 1.0374x over previous
#include <cuda_runtime.h>
#include <cuda_fp16.h>
#include <cstdint>

typedef unsigned long long ull;

// Problem constants
constexpr int NN = 100000;
constexpr int EE = 1250000;
constexpr int KTOT = 576;                 // 64 (root) + 8*64
constexpr int NK = NN * 8;                // (dst, rel) keys
constexpr int NBLK2 = (NK + 1023) / 1024; // 782 scan blocks
constexpr int NCH = 9;                    // 1 root chunk + 8 relation chunks
constexpr int AS = 72;                    // fp16 A/B smem row stride (144 B)
constexpr int EGRID = (EE + 255) / 256;   // 4883
constexpr int PG1 = (64 * KTOT) / 256;    // 144 blocks for W1 prep
constexpr int PG2 = (32 * KTOT) / 256;    // 72 blocks for W2 prep
constexpr int XG = (NN * 64) / (256 * 8); // 3125 blocks for x->fp16 convert

// ---------------- scratch ---------------------------------------------------
__device__ int g_cnt[NK];                 // zero at load; re-zeroed by k_scan
__device__ int g_rowptr[NK + 1];          // +1 sentinel (= EE)
__device__ int g_cursor[NK];
__device__ int g_epack[EE];               // src ids sorted by (dst, rel)
__device__ unsigned int g_scanflag[NBLK2];
__device__ __half g_x16[(size_t)NN * 64]; // fp16 input features
__device__ __half g_H[(size_t)NN * 64];   // fp16 hidden layer
__device__ __half g_Agg[(size_t)NN * 512];// fp16 per-relation mean aggregates
__device__ __half g_Wt1h[64 * KTOT];
__device__ __half g_Wt1l[64 * KTOT];
__device__ __half g_Wt2h[32 * KTOT];
__device__ __half g_Wt2l[32 * KTOT];

// ---------------- helpers ---------------------------------------------------
__device__ __forceinline__ uint32_t smem_u32(const void* p) {
    uint32_t a;
    asm("{ .reg .u64 t; cvta.to.shared.u64 t, %1; cvt.u32.u64 %0, t; }" : "=r"(a) : "l"(p));
    return a;
}
__device__ __forceinline__ void sts128(uint32_t a, uint32_t x, uint32_t y, uint32_t z, uint32_t w) {
    asm volatile("st.shared.v4.b32 [%0], {%1,%2,%3,%4};" :: "r"(a), "r"(x), "r"(y), "r"(z), "r"(w) : "memory");
}
__device__ __forceinline__ uint32_t lds32(uint32_t a) {
    uint32_t v;
    asm volatile("ld.shared.b32 %0, [%1];" : "=r"(v) : "r"(a));
    return v;
}
__device__ __forceinline__ uint32_t cvt2h(float lo, float hi) {
    uint32_t r;
    asm("cvt.rn.satfinite.f16x2.f32 %0, %1, %2;" : "=r"(r) : "f"(hi), "f"(lo));
    return r;
}
__device__ __forceinline__ void ldmx4(uint32_t* r, uint32_t a) {
    asm volatile("ldmatrix.sync.aligned.m8n8.x4.shared.b16 {%0,%1,%2,%3}, [%4];"
                 : "=r"(r[0]), "=r"(r[1]), "=r"(r[2]), "=r"(r[3]) : "r"(a));
}
__device__ __forceinline__ void mma16816(float* c, const uint32_t* a, uint32_t b0, uint32_t b1) {
    asm volatile("mma.sync.aligned.m16n8k16.row.col.f32.f16.f16.f32 "
                 "{%0,%1,%2,%3}, {%4,%5,%6,%7}, {%8,%9}, {%0,%1,%2,%3};"
                 : "+f"(c[0]), "+f"(c[1]), "+f"(c[2]), "+f"(c[3])
                 : "r"(a[0]), "r"(a[1]), "r"(a[2]), "r"(a[3]), "r"(b0), "r"(b1));
}

// ---------------- CSR build over keys (dst*8 + rel) --------------------------
__global__ void k_count(const int* __restrict__ dst, const int* __restrict__ et) {
    int e = blockIdx.x * blockDim.x + threadIdx.x;
    if (e < NBLK2) g_scanflag[e] = 0;
    if (e < EE) atomicAdd(&g_cnt[dst[e] * 8 + et[e]], 1);
}

__global__ void k_scan() {
    int t = threadIdx.x, b = blockIdx.x, i = b * 1024 + t;
    int lane = t & 31, wid = t >> 5;
    int orig = 0;
    if (i < NK) {
        orig = g_cnt[i];
        g_cnt[i] = 0;
    }
    int v = orig;
#pragma unroll
    for (int o = 1; o < 32; o <<= 1) {
        int nv = __shfl_up_sync(0xffffffffu, v, o);
        if (lane >= o) v += nv;
    }
    __shared__ int ws[32];
    __shared__ int s_prefix;
    if (lane == 31) ws[wid] = v;
    __syncthreads();
    if (wid == 0) {
        int wv = ws[lane];
#pragma unroll
        for (int o = 1; o < 32; o <<= 1) {
            int nv = __shfl_up_sync(0xffffffffu, wv, o);
            if (lane >= o) wv += nv;
        }
        ws[lane] = wv;
    }
    __syncthreads();
    int wpre = wid ? ws[wid - 1] : 0;
    int incl = wpre + v;
    if (t == 0) {
        int total = ws[31];
        if (b == 0) {
            atomicExch(&g_scanflag[0], ((unsigned)total << 2) | 2u);
            s_prefix = 0;
        } else {
            atomicExch(&g_scanflag[b], ((unsigned)total << 2) | 1u);
            int prefix = 0;
            for (int pb = b - 1;;) {
                unsigned wv;
                do { wv = atomicAdd(&g_scanflag[pb], 0u); } while ((wv & 3u) == 0u);
                prefix += (int)(wv >> 2);
                if ((wv & 3u) == 2u) break;
                pb--;
            }
            atomicExch(&g_scanflag[b], ((unsigned)(prefix + total) << 2) | 2u);
            s_prefix = prefix;
        }
    }
    __syncthreads();
    int prefix = s_prefix;
    if (i < NK) {
        int rv = prefix + incl - orig;
        g_rowptr[i] = rv;
        g_cursor[i] = rv;
    }
    if (i == 0) g_rowptr[NK] = EE;
}

// ------- merged: edge build + W transpose/split + x -> fp16 convert ----------
__device__ __forceinline__ void prep_one(const float* __restrict__ root,
                                         const float* __restrict__ W,
                                         __half* __restrict__ oh,
                                         __half* __restrict__ ol,
                                         int dout, int i) {
    int n = i / KTOT, k = i % KTOT;
    float v = (k < 64) ? root[k * dout + n] : W[(size_t)(k - 64) * dout + n];
    __half h = __float2half_rn(v);
    float lo = v - __half2float(h);
    oh[i] = h;
    ol[i] = __float2half_rn(lo);
}
__global__ void k_build_prep(const int* __restrict__ src, const int* __restrict__ dst,
                             const int* __restrict__ et, const float* __restrict__ x,
                             const float* __restrict__ root1, const float* __restrict__ W1,
                             const float* __restrict__ root2, const float* __restrict__ W2) {
    int b = blockIdx.x;
    if (b < EGRID) {
        int e = b * 256 + threadIdx.x;
        if (e < EE) {
            int p = atomicAdd(&g_cursor[dst[e] * 8 + et[e]], 1);
            g_epack[p] = src[e];
        }
    } else if (b < EGRID + XG) {
        size_t i = ((size_t)(b - EGRID) * 256 + threadIdx.x) * 8;
        const float4* xp = reinterpret_cast<const float4*>(x + i);
        float4 v0 = xp[0], v1 = xp[1];
        uint4 o;
        o.x = cvt2h(v0.x, v0.y);
        o.y = cvt2h(v0.z, v0.w);
        o.z = cvt2h(v1.x, v1.y);
        o.w = cvt2h(v1.z, v1.w);
        *reinterpret_cast<uint4*>(g_x16 + i) = o;
    } else if (b < EGRID + XG + PG1) {
        prep_one(root1, W1, g_Wt1h, g_Wt1l, 64, (b - EGRID - XG) * 256 + threadIdx.x);
    } else {
        prep_one(root2, W2, g_Wt2h, g_Wt2l, 32, (b - EGRID - XG - PG1) * 256 + threadIdx.x);
    }
}

// ---------------- aggregation: fp16 gather -> fp16 Agg[N][512] ---------------
// Warp = 16 nodes (4 streams x 4 sub-nodes); lane owns 16 B of the 128 B row.
// No MMA regs -> 3 CTAs/SM for 1.5x latency hiding vs the fused kernel.
__global__ __launch_bounds__(256, 3) void k_agg(const __half* __restrict__ F,
                                                __half* __restrict__ Agg) {
    int tid = threadIdx.x, w = tid >> 5, l = tid & 31;
    int jl = l & 7, ns = l >> 3;
    int m0 = blockIdx.x * 128;

    for (int r = 0; r < 8; r++) {
        int st[4], cn[4];
#pragma unroll
        for (int p = 0; p < 4; p++) {
            int mg = m0 + w * 16 + p * 4 + ns;
            if (mg < NN) {
                int key = mg * 8 + r;
                int s0 = __ldg(g_rowptr + key);
                st[p] = s0;
                cn[p] = __ldg(g_rowptr + key + 1) - s0;
            } else {
                st[p] = 0;
                cn[p] = 0;
            }
        }
        int mx = max(max(cn[0], cn[1]), max(cn[2], cn[3]));
        float4 a0[4], a1[4];
#pragma unroll
        for (int p = 0; p < 4; p++) {
            a0[p] = make_float4(0.f, 0.f, 0.f, 0.f);
            a1[p] = make_float4(0.f, 0.f, 0.f, 0.f);
        }
        int rec[4];
#pragma unroll
        for (int p = 0; p < 4; p++)
            rec[p] = (cn[p] > 0) ? __ldg(g_epack + st[p]) : -1;
        for (int j = 0; j < mx; j++) {
            uint4 v[4];
#pragma unroll
            for (int p = 0; p < 4; p++) {
                if (rec[p] >= 0)
                    v[p] = *(reinterpret_cast<const uint4*>(F + (size_t)rec[p] * 64) + jl);
            }
#pragma unroll
            for (int p = 0; p < 4; p++) {
                bool more = (j + 1 < cn[p]);
                int nr = more ? __ldg(g_epack + st[p] + j + 1) : -1;
                if (rec[p] >= 0) {
                    float2 f0 = __half22float2(*reinterpret_cast<__half2*>(&v[p].x));
                    float2 f1 = __half22float2(*reinterpret_cast<__half2*>(&v[p].y));
                    float2 f2 = __half22float2(*reinterpret_cast<__half2*>(&v[p].z));
                    float2 f3 = __half22float2(*reinterpret_cast<__half2*>(&v[p].w));
                    a0[p].x += f0.x; a0[p].y += f0.y;
                    a0[p].z += f1.x; a0[p].w += f1.y;
                    a1[p].x += f2.x; a1[p].y += f2.y;
                    a1[p].z += f3.x; a1[p].w += f3.y;
                }
                rec[p] = nr;
            }
        }
#pragma unroll
        for (int p = 0; p < 4; p++) {
            int mg = m0 + w * 16 + p * 4 + ns;
            if (mg < NN) {
                float inv = 1.0f / (float)max(cn[p], 1);
                uint4 o;
                o.x = cvt2h(a0[p].x * inv, a0[p].y * inv);
                o.y = cvt2h(a0[p].z * inv, a0[p].w * inv);
                o.z = cvt2h(a1[p].x * inv, a1[p].y * inv);
                o.w = cvt2h(a1[p].z * inv, a1[p].w * inv);
                *(reinterpret_cast<uint4*>(Agg + (size_t)mg * 512 + r * 64) + jl) = o;
            }
        }
    }
}

// ---------------- lean tiled GEMM: out = act(bias + [F|Agg] @ Wt^T) ----------
// A chunks are coalesced linear loads (prefetched 1 chunk ahead into regs,
// overlapping MMA). Low register count -> 3 CTAs/SM.
template <int DOUT, bool RELU, bool OUT16>
__global__ __launch_bounds__(256, 3) void k_gemm(
    const __half* __restrict__ F, const __half* __restrict__ Agg,
    const __half* __restrict__ Wth, const __half* __restrict__ Wtl,
    const float* __restrict__ bias, void* __restrict__ outv) {
    constexpr int NT = DOUT / 8;            // n-tiles per warp
    constexpr int BP = 256 / DOUT;          // B copy: parts per row
    constexpr int BV = (64 * 2 / BP) / 16;  // uint4 per thread per B buffer

    extern __shared__ __align__(16) char dyn[];
    uint32_t sA = smem_u32(dyn);
    uint32_t sBh = sA + 128 * AS * 2;
    uint32_t sBl = sBh + DOUT * AS * 2;

    int tid = threadIdx.x;
    int w = tid >> 5, l = tid & 31;
    int m0 = blockIdx.x * 128;

    int jl = l & 7, ns = l >> 3;

    // B copy mapping
    int bn = tid % DOUT, bpart = tid / DOUT;
    uint4 bh4[BV], bl4[BV];
    auto loadB = [&](int c) {
        size_t off = (size_t)bn * KTOT + c * 64;
        const uint4* bh = reinterpret_cast<const uint4*>(Wth + off) + bpart * BV;
        const uint4* bl = reinterpret_cast<const uint4*>(Wtl + off) + bpart * BV;
#pragma unroll
        for (int v = 0; v < BV; v++) { bh4[v] = bh[v]; bl4[v] = bl[v]; }
    };
    auto storeB = [&]() {
        uint32_t bbase = (uint32_t)(bn * (AS * 2) + bpart * (BV * 16));
#pragma unroll
        for (int v = 0; v < BV; v++) {
            sts128(sBh + bbase + v * 16, bh4[v].x, bh4[v].y, bh4[v].z, bh4[v].w);
            sts128(sBl + bbase + v * 16, bl4[v].x, bl4[v].y, bl4[v].z, bl4[v].w);
        }
    };

    // A tile: warp covers rows w*16 + p*4 + ns, lane part jl (16 B)
    uint4 av[4];
    auto loadA = [&](int c) {
#pragma unroll
        for (int p = 0; p < 4; p++) {
            int mg = m0 + w * 16 + p * 4 + ns;
            if (mg < NN) {
                const __half* base = (c == 0) ? (F + (size_t)mg * 64)
                                              : (Agg + (size_t)mg * 512 + (c - 1) * 64);
                av[p] = *(reinterpret_cast<const uint4*>(base) + jl);
            } else {
                av[p] = make_uint4(0u, 0u, 0u, 0u);
            }
        }
    };
    auto storeA = [&]() {
#pragma unroll
        for (int p = 0; p < 4; p++) {
            int nrow = w * 16 + p * 4 + ns;
            sts128(sA + (uint32_t)(nrow * (AS * 2)) + jl * 16,
                   av[p].x, av[p].y, av[p].z, av[p].w);
        }
    };

    float acc[NT][4];
#pragma unroll
    for (int t = 0; t < NT; t++)
#pragma unroll
        for (int q = 0; q < 4; q++) acc[t][q] = 0.f;

    // A ldmatrix address
    int lrow = w * 16 + (l & 7) + ((l >> 3) & 1) * 8;
    uint32_t aoff = (uint32_t)(lrow * (AS * 2)) + ((l >> 4) & 1) * 16;
    // B frag address components
    int bfn = l >> 2;
    int bfk = (l & 3) * 4;

    loadB(0);
    loadA(0);
    for (int c = 0; c < NCH; c++) {
        storeB();
        storeA();
        __syncthreads();
        if (c + 1 < NCH) { loadB(c + 1); loadA(c + 1); }
#pragma unroll
        for (int ks = 0; ks < 4; ks++) {
            uint32_t fa[4];
            ldmx4(fa, sA + aoff + ks * 32);
#pragma unroll
            for (int t = 0; t < NT; t++) {
                uint32_t ba = (uint32_t)((t * 8 + bfn) * (AS * 2)) + ks * 32 + bfk;
                uint32_t bh0 = lds32(sBh + ba), bh1 = lds32(sBh + ba + 16);
                uint32_t bl0 = lds32(sBl + ba), bl1 = lds32(sBl + ba + 16);
                mma16816(acc[t], fa, bh0, bh1);
                mma16816(acc[t], fa, bl0, bl1);
            }
        }
        __syncthreads();
    }

    // epilogue
    int r0 = m0 + w * 16 + (l >> 2);
    int cb = (l & 3) * 2;
#pragma unroll
    for (int t = 0; t < NT; t++) {
        int n = t * 8 + cb;
        float b0 = __ldg(bias + n), b1 = __ldg(bias + n + 1);
        float v0 = acc[t][0] + b0, v1 = acc[t][1] + b1;
        float v2 = acc[t][2] + b0, v3 = acc[t][3] + b1;
        if (RELU) {
            v0 = fmaxf(v0, 0.f); v1 = fmaxf(v1, 0.f);
            v2 = fmaxf(v2, 0.f); v3 = fmaxf(v3, 0.f);
        }
        if (OUT16) {
            __half* o16 = reinterpret_cast<__half*>(outv);
            if (r0 < NN)
                *reinterpret_cast<uint32_t*>(o16 + (size_t)r0 * DOUT + n) = cvt2h(v0, v1);
            if (r0 + 8 < NN)
                *reinterpret_cast<uint32_t*>(o16 + (size_t)(r0 + 8) * DOUT + n) = cvt2h(v2, v3);
        } else {
            float* of = reinterpret_cast<float*>(outv);
            if (r0 < NN)
                *reinterpret_cast<float2*>(of + (size_t)r0 * DOUT + n) = make_float2(v0, v1);
            if (r0 + 8 < NN)
                *reinterpret_cast<float2*>(of + (size_t)(r0 + 8) * DOUT + n) = make_float2(v2, v3);
        }
    }
}

// ---------------- launch ----------------------------------------------------
extern "C" void kernel_launch(void* const* d_in, const int* in_sizes, int n_in,
                              void* d_out, int out_size) {
    const float* x     = (const float*)d_in[0];
    const float* W1    = (const float*)d_in[1];
    const float* root1 = (const float*)d_in[2];
    const float* b1    = (const float*)d_in[3];
    const float* W2    = (const float*)d_in[4];
    const float* root2 = (const float*)d_in[5];
    const float* b2    = (const float*)d_in[6];
    const int*   src   = (const int*)d_in[7];
    const int*   dst   = (const int*)d_in[8];
    const int*   et    = (const int*)d_in[9];

    __half *H, *x16, *Agg, *w1h, *w1l, *w2h, *w2l;
    cudaGetSymbolAddress((void**)&H, g_H);
    cudaGetSymbolAddress((void**)&x16, g_x16);
    cudaGetSymbolAddress((void**)&Agg, g_Agg);
    cudaGetSymbolAddress((void**)&w1h, g_Wt1h);
    cudaGetSymbolAddress((void**)&w1l, g_Wt1l);
    cudaGetSymbolAddress((void**)&w2h, g_Wt2h);
    cudaGetSymbolAddress((void**)&w2l, g_Wt2l);

    const int ggrid = (NN + 127) / 128;
    const int smA = 128 * AS * 2;
    const int smem64 = smA + 2 * 64 * AS * 2;   // 36864
    const int smem32 = smA + 2 * 32 * AS * 2;   // 27648

    static bool attr_done = false;
    if (!attr_done) {
        cudaFuncSetAttribute(k_gemm<64, true, true>,
                             cudaFuncAttributeMaxDynamicSharedMemorySize, smem64);
        cudaFuncSetAttribute(k_gemm<32, false, false>,
                             cudaFuncAttributeMaxDynamicSharedMemorySize, smem32);
        attr_done = true;
    }

    // CSR build over (dst, rel) keys (g_cnt pre-zeroed by previous call's k_scan)
    k_count<<<EGRID, 256>>>(dst, et);
    k_scan<<<NBLK2, 1024>>>();
    k_build_prep<<<EGRID + XG + PG1 + PG2, 256>>>(src, dst, et, x,
                                                  root1, W1, root2, W2);

    // Layer 1: aggregate then GEMM (H written fp16)
    k_agg<<<ggrid, 256>>>(x16, Agg);
    k_gemm<64, true, true><<<ggrid, 256, smem64>>>(x16, Agg, w1h, w1l, b1, H);

    // Layer 2: aggregate H then GEMM -> fp32 output
    k_agg<<<ggrid, 256>>>(H, Agg);
    k_gemm<32, false, false><<<ggrid, 256, smem32>>>(H, Agg, w2h, w2l, b2, d_out);
}